// round 4
// baseline (speedup 1.0000x reference)
#include <cuda_runtime.h>
#include <math.h>

#define BB   4
#define SS   2048
#define DD   1024
#define HH   16
#define DHH  64
#define MTOT (BB*SS)          // 8192
#define MASKVAL (-1e30f)

// ---------------- scratch (static device arrays; no allocation) -------------
__device__ float g_q  [(size_t)MTOT*DD];
__device__ float g_k  [(size_t)MTOT*DD];
__device__ float g_kt [(size_t)MTOT*DD];   // K transposed: [B*H][DH][S]
__device__ float g_v  [(size_t)MTOT*DD];
__device__ float g_ctx[(size_t)MTOT*DD];
__device__ unsigned char g_mask8[(size_t)SS*SS];
__device__ int   g_mask_kind;              // 0 = byte elements, 1 = 4-byte elements

// ---------------- mask dtype detection + canonicalization --------------------
__global__ void detect_mask_kind(const unsigned int* __restrict__ m) {
    int lane = threadIdx.x;
    bool word_like = true;
    for (int i = lane; i < 256; i += 32) {
        unsigned int w = m[i];
        word_like = word_like && (w <= 1u || w == 0x3F800000u);
    }
    word_like = __all_sync(0xffffffffu, word_like);
    if (lane == 0) g_mask_kind = word_like ? 1 : 0;
}

__global__ void convert_mask(const void* __restrict__ mp) {
    const int kind = g_mask_kind;
    const int N4 = SS*SS/4;
    int idx = blockIdx.x * blockDim.x + threadIdx.x;
    for (int i = idx; i < N4; i += gridDim.x * blockDim.x) {
        uchar4 o;
        if (kind == 0) {
            o = ((const uchar4*)mp)[i];
        } else {
            const unsigned int* w = (const unsigned int*)mp + (size_t)i*4;
            o.x = (w[0] != 0u); o.y = (w[1] != 0u);
            o.z = (w[2] != 0u); o.w = (w[3] != 0u);
        }
        ((uchar4*)g_mask8)[i] = o;
    }
}

// ---------------- GEMM: C[M,1024] = A[M,1024] @ W[1024,1024] + bias ----------
#define GBM 128
#define GBN 128
#define GBK 16
#define GSP 132   // padded smem stride (floats)

__device__ __forceinline__ void gemm_body(const float* __restrict__ A,
                                          const float* __restrict__ W,
                                          const float* __restrict__ bias,
                                          float* __restrict__ C) {
    __shared__ float As[GBK][GSP];   // transposed: As[k][m]
    __shared__ float Ws[GBK][GSP];   // Ws[k][n]
    const int t  = threadIdx.x;
    const int tx = t & 15, ty = t >> 4;
    const int row0 = blockIdx.y * GBM;
    const int col0 = blockIdx.x * GBN;

    float acc[2][2][4][4];
#pragma unroll
    for (int a = 0; a < 2; ++a)
#pragma unroll
        for (int b2 = 0; b2 < 2; ++b2)
#pragma unroll
            for (int i = 0; i < 4; ++i)
#pragma unroll
                for (int j = 0; j < 4; ++j) acc[a][b2][i][j] = 0.f;

    for (int k0 = 0; k0 < DD; k0 += GBK) {
#pragma unroll
        for (int c = 0; c < 2; ++c) {              // A tile (store transposed)
            int f4 = t + 256*c;                    // 0..511
            int r  = f4 >> 2;                      // 0..127
            int kq = (f4 & 3) * 4;                 // 0,4,8,12
            float4 va = *reinterpret_cast<const float4*>(
                A + (size_t)(row0 + r)*DD + k0 + kq);
            As[kq+0][r] = va.x; As[kq+1][r] = va.y;
            As[kq+2][r] = va.z; As[kq+3][r] = va.w;
        }
#pragma unroll
        for (int c = 0; c < 2; ++c) {              // W tile
            int f4 = t + 256*c;
            int kk = f4 >> 5;                      // 0..15
            int cq = (f4 & 31) * 4;                // 0..124
            *reinterpret_cast<float4*>(&Ws[kk][cq]) =
                *reinterpret_cast<const float4*>(W + (size_t)(k0 + kk)*DD + col0 + cq);
        }
        __syncthreads();
#pragma unroll
        for (int kk = 0; kk < GBK; ++kk) {
            float a0[4], a1[4], b0[4], b1[4];
            *reinterpret_cast<float4*>(a0) = *reinterpret_cast<const float4*>(&As[kk][4*ty]);
            *reinterpret_cast<float4*>(a1) = *reinterpret_cast<const float4*>(&As[kk][64 + 4*ty]);
            *reinterpret_cast<float4*>(b0) = *reinterpret_cast<const float4*>(&Ws[kk][4*tx]);
            *reinterpret_cast<float4*>(b1) = *reinterpret_cast<const float4*>(&Ws[kk][64 + 4*tx]);
#pragma unroll
            for (int i = 0; i < 4; ++i)
#pragma unroll
                for (int j = 0; j < 4; ++j) {
                    acc[0][0][i][j] += a0[i]*b0[j];
                    acc[0][1][i][j] += a0[i]*b1[j];
                    acc[1][0][i][j] += a1[i]*b0[j];
                    acc[1][1][i][j] += a1[i]*b1[j];
                }
        }
        __syncthreads();
    }

    float bb[2][4];
    *reinterpret_cast<float4*>(bb[0]) = *reinterpret_cast<const float4*>(bias + col0 + 4*tx);
    *reinterpret_cast<float4*>(bb[1]) = *reinterpret_cast<const float4*>(bias + col0 + 64 + 4*tx);
#pragma unroll
    for (int ri = 0; ri < 2; ++ri)
#pragma unroll
        for (int i = 0; i < 4; ++i) {
            size_t r = (size_t)(row0 + ri*64 + 4*ty + i);
#pragma unroll
            for (int cj = 0; cj < 2; ++cj) {
                float4 o4;
                o4.x = acc[ri][cj][i][0] + bb[cj][0];
                o4.y = acc[ri][cj][i][1] + bb[cj][1];
                o4.z = acc[ri][cj][i][2] + bb[cj][2];
                o4.w = acc[ri][cj][i][3] + bb[cj][3];
                *reinterpret_cast<float4*>(C + r*DD + col0 + cj*64 + 4*tx) = o4;
            }
        }
}

__global__ __launch_bounds__(256, 2) void gemm_qkv_kernel(
    const float* __restrict__ A,
    const float* __restrict__ Wq, const float* __restrict__ bq,
    const float* __restrict__ Wk, const float* __restrict__ bk,
    const float* __restrict__ Wv, const float* __restrict__ bv) {
    const float* W; const float* bias; float* C;
    if (blockIdx.z == 0)      { W = Wq; bias = bq; C = g_q; }
    else if (blockIdx.z == 1) { W = Wk; bias = bk; C = g_k; }
    else                      { W = Wv; bias = bv; C = g_v; }
    gemm_body(A, W, bias, C);
}

__global__ __launch_bounds__(256, 2) void gemm_out_kernel(
    const float* __restrict__ Wo, const float* __restrict__ bo,
    float* __restrict__ out) {
    gemm_body(g_ctx, Wo, bo, out);
}

// ---------------- K transpose: [B,S,D] -> [B*H][DH][S] -----------------------
__global__ void transpose_k_kernel() {
    __shared__ float tile[32][33];
    int bh = blockIdx.z;                 // b*H + h
    int b  = bh >> 4, h = bh & 15;
    int s0 = blockIdx.x * 32, d0 = blockIdx.y * 32;
    int tx = threadIdx.x, ty = threadIdx.y;     // (32, 8)
#pragma unroll
    for (int i = ty; i < 32; i += 8)
        tile[i][tx] = g_k[(size_t)(b*SS + s0 + i)*DD + h*DHH + d0 + tx];
    __syncthreads();
#pragma unroll
    for (int i = ty; i < 32; i += 8)
        g_kt[((size_t)bh*DHH + d0 + i)*SS + s0 + tx] = tile[tx][i];
}

// ---------------- flash attention: 128q x 64k tiles, online softmax ----------
// smem: Qs[64][128] (dh,q) | Ks[64][64] (dh,key) | Vs[64][64] (key,dh) | Ps[128][64]
#define ATTN_SMEM ((64*128 + 64*64 + 64*64 + 128*64) * 4)

__global__ __launch_bounds__(256, 2) void attn_kernel() {
    extern __shared__ float sm[];
    float* Qs = sm;                 // [64][128]
    float* Ks = sm + 64*128;        // [64][64]
    float* Vs = Ks + 64*64;         // [64][64]
    float* Ps = Vs + 64*64;         // [128][64]

    const int t  = threadIdx.x;
    const int tx = t & 15, ty = t >> 4;
    const int q0 = blockIdx.x * 128;
    const int bh = blockIdx.y;
    const int b  = bh >> 4, h = bh & 15;

    const size_t qbase  = ((size_t)(b*SS) + q0)*DD + (size_t)h*DHH;
    const size_t ktbase = (size_t)bh*DHH*SS;                  // g_kt[bh][dh][s]
    const size_t vbase  = (size_t)(b*SS)*DD + (size_t)h*DHH;

    // load Q tile transposed: Qs[dh][q]
#pragma unroll
    for (int c = 0; c < 8; ++c) {
        int idx = t + 256*c;            // 0..2047 float4s
        int dh4 = idx & 15, q = idx >> 4;
        float4 v = *reinterpret_cast<const float4*>(g_q + qbase + (size_t)q*DD + 4*dh4);
        Qs[(4*dh4+0)*128 + q] = v.x;
        Qs[(4*dh4+1)*128 + q] = v.y;
        Qs[(4*dh4+2)*128 + q] = v.z;
        Qs[(4*dh4+3)*128 + q] = v.w;
    }

    float m_run[8], l_run[8], acc_o[8][4];
#pragma unroll
    for (int i = 0; i < 8; ++i) {
        m_run[i] = MASKVAL; l_run[i] = 0.f;
#pragma unroll
        for (int j = 0; j < 4; ++j) acc_o[i][j] = 0.f;
    }

    for (int k0 = 0; k0 < SS; k0 += 64) {
        __syncthreads();   // protect Ks/Vs/Ps from previous iteration's readers

        // K tile: Ks[dh][key]
#pragma unroll
        for (int c = 0; c < 4; ++c) {
            int idx = t + 256*c; int s4 = idx & 15, dh = idx >> 4;
            *reinterpret_cast<float4*>(Ks + dh*64 + 4*s4) =
                *reinterpret_cast<const float4*>(g_kt + ktbase + (size_t)dh*SS + k0 + 4*s4);
        }
        // V tile: Vs[key][dh]
#pragma unroll
        for (int c = 0; c < 4; ++c) {
            int idx = t + 256*c; int d4 = idx & 15, key = idx >> 4;
            *reinterpret_cast<float4*>(Vs + key*64 + 4*d4) =
                *reinterpret_cast<const float4*>(g_v + vbase + (size_t)(k0+key)*DD + 4*d4);
        }
        // mask bytes straight to registers (4 keys per row)
        unsigned int mrow[8];
#pragma unroll
        for (int i = 0; i < 8; ++i)
            mrow[i] = *reinterpret_cast<const unsigned int*>(
                g_mask8 + (size_t)(q0 + 8*ty + i)*SS + k0 + 4*tx);
        __syncthreads();

        // S = (Q K^T) * scale, masked
        float s_[8][4];
#pragma unroll
        for (int i = 0; i < 8; ++i)
#pragma unroll
            for (int j = 0; j < 4; ++j) s_[i][j] = 0.f;

#pragma unroll 8
        for (int dh = 0; dh < 64; ++dh) {
            float4 qa = *reinterpret_cast<const float4*>(Qs + dh*128 + 8*ty);
            float4 qb = *reinterpret_cast<const float4*>(Qs + dh*128 + 8*ty + 4);
            float4 kf = *reinterpret_cast<const float4*>(Ks + dh*64 + 4*tx);
            float qr[8] = {qa.x, qa.y, qa.z, qa.w, qb.x, qb.y, qb.z, qb.w};
            float kr[4] = {kf.x, kf.y, kf.z, kf.w};
#pragma unroll
            for (int i = 0; i < 8; ++i)
#pragma unroll
                for (int j = 0; j < 4; ++j) s_[i][j] += qr[i]*kr[j];
        }

        // online softmax update (row group = 16 lanes sharing ty)
#pragma unroll
        for (int i = 0; i < 8; ++i) {
#pragma unroll
            for (int j = 0; j < 4; ++j) {
                float sv = s_[i][j] * 0.125f;
                if (((mrow[i] >> (8*j)) & 0xFF) == 0) sv = MASKVAL;
                s_[i][j] = sv;
            }
            float tm = fmaxf(fmaxf(s_[i][0], s_[i][1]), fmaxf(s_[i][2], s_[i][3]));
#pragma unroll
            for (int o = 1; o < 16; o <<= 1)
                tm = fmaxf(tm, __shfl_xor_sync(0xffffffffu, tm, o));
            float mn    = fmaxf(m_run[i], tm);
            float alpha = __expf(m_run[i] - mn);     // exp(0)=1 if both MASKVAL
            float p[4], psum = 0.f;
#pragma unroll
            for (int j = 0; j < 4; ++j) { p[j] = __expf(s_[i][j] - mn); psum += p[j]; }
#pragma unroll
            for (int o = 1; o < 16; o <<= 1)
                psum += __shfl_xor_sync(0xffffffffu, psum, o);
            l_run[i] = l_run[i]*alpha + psum;
            m_run[i] = mn;
#pragma unroll
            for (int j = 0; j < 4; ++j) acc_o[i][j] *= alpha;
            float4 pv = make_float4(p[0], p[1], p[2], p[3]);
            *reinterpret_cast<float4*>(Ps + (8*ty + i)*64 + 4*tx) = pv;
        }
        __syncthreads();

        // acc_o += P @ V
#pragma unroll 4
        for (int kk = 0; kk < 64; kk += 4) {
            float4 vv0 = *reinterpret_cast<const float4*>(Vs + (kk+0)*64 + 4*tx);
            float4 vv1 = *reinterpret_cast<const float4*>(Vs + (kk+1)*64 + 4*tx);
            float4 vv2 = *reinterpret_cast<const float4*>(Vs + (kk+2)*64 + 4*tx);
            float4 vv3 = *reinterpret_cast<const float4*>(Vs + (kk+3)*64 + 4*tx);
#pragma unroll
            for (int i = 0; i < 8; ++i) {
                float4 pp = *reinterpret_cast<const float4*>(Ps + (8*ty + i)*64 + kk);
                acc_o[i][0] += pp.x*vv0.x + pp.y*vv1.x + pp.z*vv2.x + pp.w*vv3.x;
                acc_o[i][1] += pp.x*vv0.y + pp.y*vv1.y + pp.z*vv2.y + pp.w*vv3.y;
                acc_o[i][2] += pp.x*vv0.z + pp.y*vv1.z + pp.z*vv2.z + pp.w*vv3.z;
                acc_o[i][3] += pp.x*vv0.w + pp.y*vv1.w + pp.z*vv2.w + pp.w*vv3.w;
            }
        }
    }

    // normalize + write ctx as [B,S,H,DH] == [M][D]
#pragma unroll
    for (int i = 0; i < 8; ++i) {
        float inv = 1.f / l_run[i];
        float4 o4 = make_float4(acc_o[i][0]*inv, acc_o[i][1]*inv,
                                acc_o[i][2]*inv, acc_o[i][3]*inv);
        *reinterpret_cast<float4*>(
            g_ctx + ((size_t)(b*SS) + q0 + 8*ty + i)*DD + (size_t)h*DHH + 4*tx) = o4;
    }
}

// ---------------- launch -----------------------------------------------------
extern "C" void kernel_launch(void* const* d_in, const int* in_sizes, int n_in,
                              void* d_out, int out_size) {
    const float* hs = (const float*)d_in[0];
    const void*  mk = d_in[1];
    const float* Wq = (const float*)d_in[2]; const float* bq = (const float*)d_in[3];
    const float* Wk = (const float*)d_in[4]; const float* bk = (const float*)d_in[5];
    const float* Wv = (const float*)d_in[6]; const float* bv = (const float*)d_in[7];
    const float* Wo = (const float*)d_in[8]; const float* bo = (const float*)d_in[9];
    float* out = (float*)d_out;

    static bool attr_set = false;
    if (!attr_set) {
        cudaFuncSetAttribute(attn_kernel,
                             cudaFuncAttributeMaxDynamicSharedMemorySize, ATTN_SMEM);
        attr_set = true;
    }

    detect_mask_kind<<<1, 32>>>((const unsigned int*)mk);
    convert_mask<<<1024, 256>>>(mk);

    gemm_qkv_kernel<<<dim3(DD/GBN, MTOT/GBM, 3), 256>>>(hs, Wq, bq, Wk, bk, Wv, bv);
    transpose_k_kernel<<<dim3(SS/32, DHH/32, BB*HH), dim3(32, 8)>>>();
    attn_kernel<<<dim3(SS/128, BB*HH), 256, ATTN_SMEM>>>();
    gemm_out_kernel<<<dim3(DD/GBN, MTOT/GBM), 256>>>(Wo, bo, out);
}

// round 6
// speedup vs baseline: 1.2990x; 1.2990x over previous
#include <cuda_runtime.h>
#include <math.h>
#include <stdint.h>

#define BB   4
#define SS   2048
#define DD   1024
#define HH   16
#define DHH  64
#define MTOT (BB*SS)          // 8192
#define MASKVAL (-1e30f)

// ---------------- scratch (static device arrays; no allocation) -------------
__device__ float g_q  [(size_t)MTOT*DD];
__device__ float g_k  [(size_t)MTOT*DD];
__device__ float g_kt [(size_t)MTOT*DD];   // K transposed: [B*H][DH][S]
__device__ float g_v  [(size_t)MTOT*DD];
__device__ float g_ctx[(size_t)MTOT*DD];
__device__ float g_wt [4*(size_t)DD*DD];   // W transposed to [N][K], tf32-rounded
__device__ unsigned char g_mask8[(size_t)SS*SS];
__device__ int   g_mask_kind;

__device__ __forceinline__ float to_tf32(float x) {
    float r;
    asm("cvt.rna.tf32.f32 %0, %1;" : "=f"(r) : "f"(x));
    return r;
}

// m16n8k8 tf32 warp MMA (Ampere-class; compiles at baseline sm_103 target)
__device__ __forceinline__ void mma_tf32(float4& d, const uint32_t a[4],
                                         const uint32_t b[2]) {
    asm volatile(
        "mma.sync.aligned.m16n8k8.row.col.f32.tf32.tf32.f32 "
        "{%0,%1,%2,%3}, {%4,%5,%6,%7}, {%8,%9}, {%0,%1,%2,%3};"
        : "+f"(d.x), "+f"(d.y), "+f"(d.z), "+f"(d.w)
        : "r"(a[0]), "r"(a[1]), "r"(a[2]), "r"(a[3]), "r"(b[0]), "r"(b[1]));
}

// ---------------- mask dtype detection + canonicalization --------------------
__global__ void detect_mask_kind(const unsigned int* __restrict__ m) {
    int lane = threadIdx.x;
    bool word_like = true;
    for (int i = lane; i < 256; i += 32) {
        unsigned int w = m[i];
        word_like = word_like && (w <= 1u || w == 0x3F800000u);
    }
    word_like = __all_sync(0xffffffffu, word_like);
    if (lane == 0) g_mask_kind = word_like ? 1 : 0;
}

__global__ void convert_mask(const void* __restrict__ mp) {
    const int kind = g_mask_kind;
    const int N4 = SS*SS/4;
    int idx = blockIdx.x * blockDim.x + threadIdx.x;
    for (int i = idx; i < N4; i += gridDim.x * blockDim.x) {
        uchar4 o;
        if (kind == 0) {
            o = ((const uchar4*)mp)[i];
        } else {
            const unsigned int* w = (const unsigned int*)mp + (size_t)i*4;
            o.x = (w[0] != 0u); o.y = (w[1] != 0u);
            o.z = (w[2] != 0u); o.w = (w[3] != 0u);
        }
        ((uchar4*)g_mask8)[i] = o;
    }
}

// ---------------- weight transpose: W[K,N] -> WT[N,K] (tf32-rounded) ---------
__global__ void transpose_w_kernel(const float* __restrict__ W0, const float* __restrict__ W1,
                                   const float* __restrict__ W2, const float* __restrict__ W3) {
    __shared__ float tile[32][33];
    int z = blockIdx.z;
    const float* W = (z == 0) ? W0 : (z == 1) ? W1 : (z == 2) ? W2 : W3;
    float* WT = g_wt + (size_t)z*DD*DD;
    int n0 = blockIdx.x * 32, k0 = blockIdx.y * 32;
    int tx = threadIdx.x, ty = threadIdx.y;      // (32, 8)
#pragma unroll
    for (int i = ty; i < 32; i += 8)
        tile[i][tx] = to_tf32(W[(size_t)(k0 + i)*DD + n0 + tx]);
    __syncthreads();
#pragma unroll
    for (int i = ty; i < 32; i += 8)
        WT[(size_t)(n0 + i)*DD + k0 + tx] = tile[tx][i];
}

// ---------------- tf32 mma.sync GEMM: C[M,1024] = A @ WT^T + bias ------------
// CTA 128x128, 8 warps (4m x 2n), warp tile 32x64. K-chunk 32, double buffer.
// Smem is fragment-permuted: A [ks][mt(8)][lane]*4w, B [ks][nt(16)][lane]*2w.
#define GT_SMEM (2*8192*4)     // 64 KB

__device__ __forceinline__ void gemm_mma_body(const float* __restrict__ A,
                                              const float* __restrict__ Bt,
                                              const float* __restrict__ bias,
                                              float* __restrict__ C,
                                              float* sm) {
    const int t    = threadIdx.x;
    const int lane = t & 31;
    const int wid  = t >> 5;
    const int wm   = wid >> 1;          // 0..3  (m position)
    const int wn   = wid & 1;           // 0..1  (n position)
    const int row0 = blockIdx.y * 128;
    const int col0 = blockIdx.x * 128;

    // staging-load indices: i = t + 256*c -> row = i>>3 (0..127), kq = i&7
    const int srow = t >> 3;            // rows t>>3, +32, +64, +96
    const int skq  = t & 7;             // k-quad (4 floats)

    float4 ra[4], rb[4];

    // ---- helpers as lambdas (inlined) ----
    auto ldg_chunk = [&](int k0c) {
#pragma unroll
        for (int c = 0; c < 4; ++c) {
            int r = srow + 32*c;
            ra[c] = *reinterpret_cast<const float4*>(A  + (size_t)(row0 + r)*DD + k0c + skq*4);
            rb[c] = *reinterpret_cast<const float4*>(Bt + (size_t)(col0 + r)*DD + k0c + skq*4);
        }
    };
    auto sts_chunk = [&](float* buf) {
        float* As = buf;                // 4096 floats
        float* Bs = buf + 4096;
#pragma unroll
        for (int c = 0; c < 4; ++c) {
            int r = srow + 32*c;
            // A: mt = r>>4, mr = r&15 -> frag lane r' = mr&7, half = mr>>3
            int mt = r >> 4, mr = r & 15, fr = mr & 7, half = mr >> 3;
            int nt = r >> 3, nr = r & 7;
            float va[4] = {ra[c].x, ra[c].y, ra[c].z, ra[c].w};
            float vb[4] = {rb[c].x, rb[c].y, rb[c].z, rb[c].w};
#pragma unroll
            for (int e = 0; e < 4; ++e) {
                int k  = skq*4 + e;          // 0..31
                int ks = k >> 3, c8 = k & 7;
                int tf = fr*4 + (c8 & 3);
                int j  = half + ((c8 >> 2) << 1);
                As[(((ks*8 + mt)*32 + tf) << 2) + j] = to_tf32(va[e]);
                int tg = nr*4 + (c8 & 3);
                int jb = c8 >> 2;
                Bs[(((ks*16 + nt)*32 + tg) << 1) + jb] = vb[e];
            }
        }
    };

    float4 acc[2][8];
#pragma unroll
    for (int i = 0; i < 2; ++i)
#pragma unroll
        for (int j = 0; j < 8; ++j) acc[i][j] = make_float4(0.f, 0.f, 0.f, 0.f);

    ldg_chunk(0);
    sts_chunk(sm);
    __syncthreads();

    for (int c = 0; c < 32; ++c) {
        const float* buf = sm + (c & 1)*8192;
        const float* As = buf;
        const float* Bs = buf + 4096;
        if (c + 1 < 32) ldg_chunk((c + 1) * 32);

#pragma unroll
        for (int ks = 0; ks < 4; ++ks) {
            uint32_t af[2][4], bf[8][2];
#pragma unroll
            for (int mt2 = 0; mt2 < 2; ++mt2) {
                float4 a4 = *reinterpret_cast<const float4*>(
                    As + (((ks*8 + (wm*2 + mt2))*32 + lane) << 2));
                af[mt2][0] = __float_as_uint(a4.x);
                af[mt2][1] = __float_as_uint(a4.y);
                af[mt2][2] = __float_as_uint(a4.z);
                af[mt2][3] = __float_as_uint(a4.w);
            }
#pragma unroll
            for (int nt2 = 0; nt2 < 8; ++nt2) {
                float2 b2 = *reinterpret_cast<const float2*>(
                    Bs + (((ks*16 + (wn*8 + nt2))*32 + lane) << 1));
                bf[nt2][0] = __float_as_uint(b2.x);
                bf[nt2][1] = __float_as_uint(b2.y);
            }
#pragma unroll
            for (int mt2 = 0; mt2 < 2; ++mt2)
#pragma unroll
                for (int nt2 = 0; nt2 < 8; ++nt2)
                    mma_tf32(acc[mt2][nt2], af[mt2], bf[nt2]);
        }
        __syncthreads();
        if (c + 1 < 32) sts_chunk(sm + ((c + 1) & 1)*8192);
        __syncthreads();
    }

    // epilogue: c0,c1 at (g, tg*2..+1), c2,c3 at (g+8, ...)
    const int g  = lane >> 2, tg = lane & 3;
#pragma unroll
    for (int mt2 = 0; mt2 < 2; ++mt2) {
        size_t rA = (size_t)(row0 + (wm*2 + mt2)*16 + g);
        size_t rB = rA + 8;
#pragma unroll
        for (int nt2 = 0; nt2 < 8; ++nt2) {
            int col = col0 + (wn*8 + nt2)*8 + tg*2;
            float2 b2 = *reinterpret_cast<const float2*>(bias + col);
            float2 o0 = make_float2(acc[mt2][nt2].x + b2.x, acc[mt2][nt2].y + b2.y);
            float2 o1 = make_float2(acc[mt2][nt2].z + b2.x, acc[mt2][nt2].w + b2.y);
            *reinterpret_cast<float2*>(C + rA*DD + col) = o0;
            *reinterpret_cast<float2*>(C + rB*DD + col) = o1;
        }
    }
}

__global__ __launch_bounds__(256) void gemm_qkv_mma(
    const float* __restrict__ A,
    const float* __restrict__ bq, const float* __restrict__ bk,
    const float* __restrict__ bv) {
    extern __shared__ float smf[];
    int z = blockIdx.z;
    const float* Bt   = g_wt + (size_t)z*DD*DD;
    const float* bias = (z == 0) ? bq : (z == 1) ? bk : bv;
    float* C          = (z == 0) ? g_q : (z == 1) ? g_k : g_v;
    gemm_mma_body(A, Bt, bias, C, smf);
}

__global__ __launch_bounds__(256) void gemm_o_mma(
    const float* __restrict__ bo, float* __restrict__ out) {
    extern __shared__ float smf[];
    gemm_mma_body(g_ctx, g_wt + 3*(size_t)DD*DD, bo, out, smf);
}

// ---------------- K transpose: [B,S,D] -> [B*H][DH][S] -----------------------
__global__ void transpose_k_kernel() {
    __shared__ float tile[32][33];
    int bh = blockIdx.z;
    int b  = bh >> 4, h = bh & 15;
    int s0 = blockIdx.x * 32, d0 = blockIdx.y * 32;
    int tx = threadIdx.x, ty = threadIdx.y;
#pragma unroll
    for (int i = ty; i < 32; i += 8)
        tile[i][tx] = g_k[(size_t)(b*SS + s0 + i)*DD + h*DHH + d0 + tx];
    __syncthreads();
#pragma unroll
    for (int i = ty; i < 32; i += 8)
        g_kt[((size_t)bh*DHH + d0 + i)*SS + s0 + tx] = tile[tx][i];
}

// ---------------- flash attention: 128q x 64k tiles, online softmax ----------
#define ATTN_SMEM ((64*128 + 64*64 + 64*64 + 128*64) * 4)

__global__ __launch_bounds__(256, 2) void attn_kernel() {
    extern __shared__ float sm[];
    float* Qs = sm;                 // [64][128]
    float* Ks = sm + 64*128;        // [64][64]
    float* Vs = Ks + 64*64;         // [64][64]
    float* Ps = Vs + 64*64;         // [128][64]

    const int t  = threadIdx.x;
    const int tx = t & 15, ty = t >> 4;
    const int q0 = blockIdx.x * 128;
    const int bh = blockIdx.y;
    const int b  = bh >> 4, h = bh & 15;

    const size_t qbase  = ((size_t)(b*SS) + q0)*DD + (size_t)h*DHH;
    const size_t ktbase = (size_t)bh*DHH*SS;
    const size_t vbase  = (size_t)(b*SS)*DD + (size_t)h*DHH;

#pragma unroll
    for (int c = 0; c < 8; ++c) {
        int idx = t + 256*c;
        int dh4 = idx & 15, q = idx >> 4;
        float4 v = *reinterpret_cast<const float4*>(g_q + qbase + (size_t)q*DD + 4*dh4);
        Qs[(4*dh4+0)*128 + q] = v.x;
        Qs[(4*dh4+1)*128 + q] = v.y;
        Qs[(4*dh4+2)*128 + q] = v.z;
        Qs[(4*dh4+3)*128 + q] = v.w;
    }

    float m_run[8], l_run[8], acc_o[8][4];
#pragma unroll
    for (int i = 0; i < 8; ++i) {
        m_run[i] = MASKVAL; l_run[i] = 0.f;
#pragma unroll
        for (int j = 0; j < 4; ++j) acc_o[i][j] = 0.f;
    }

    for (int k0 = 0; k0 < SS; k0 += 64) {
        __syncthreads();
#pragma unroll
        for (int c = 0; c < 4; ++c) {
            int idx = t + 256*c; int s4 = idx & 15, dh = idx >> 4;
            *reinterpret_cast<float4*>(Ks + dh*64 + 4*s4) =
                *reinterpret_cast<const float4*>(g_kt + ktbase + (size_t)dh*SS + k0 + 4*s4);
        }
#pragma unroll
        for (int c = 0; c < 4; ++c) {
            int idx = t + 256*c; int d4 = idx & 15, key = idx >> 4;
            *reinterpret_cast<float4*>(Vs + key*64 + 4*d4) =
                *reinterpret_cast<const float4*>(g_v + vbase + (size_t)(k0+key)*DD + 4*d4);
        }
        unsigned int mrow[8];
#pragma unroll
        for (int i = 0; i < 8; ++i)
            mrow[i] = *reinterpret_cast<const unsigned int*>(
                g_mask8 + (size_t)(q0 + 8*ty + i)*SS + k0 + 4*tx);
        __syncthreads();

        float s_[8][4];
#pragma unroll
        for (int i = 0; i < 8; ++i)
#pragma unroll
            for (int j = 0; j < 4; ++j) s_[i][j] = 0.f;

#pragma unroll 8
        for (int dh = 0; dh < 64; ++dh) {
            float4 qa = *reinterpret_cast<const float4*>(Qs + dh*128 + 8*ty);
            float4 qb = *reinterpret_cast<const float4*>(Qs + dh*128 + 8*ty + 4);
            float4 kf = *reinterpret_cast<const float4*>(Ks + dh*64 + 4*tx);
            float qr[8] = {qa.x, qa.y, qa.z, qa.w, qb.x, qb.y, qb.z, qb.w};
            float kr[4] = {kf.x, kf.y, kf.z, kf.w};
#pragma unroll
            for (int i = 0; i < 8; ++i)
#pragma unroll
                for (int j = 0; j < 4; ++j) s_[i][j] += qr[i]*kr[j];
        }

#pragma unroll
        for (int i = 0; i < 8; ++i) {
#pragma unroll
            for (int j = 0; j < 4; ++j) {
                float sv = s_[i][j] * 0.125f;
                if (((mrow[i] >> (8*j)) & 0xFF) == 0) sv = MASKVAL;
                s_[i][j] = sv;
            }
            float tm = fmaxf(fmaxf(s_[i][0], s_[i][1]), fmaxf(s_[i][2], s_[i][3]));
#pragma unroll
            for (int o = 1; o < 16; o <<= 1)
                tm = fmaxf(tm, __shfl_xor_sync(0xffffffffu, tm, o));
            float mn    = fmaxf(m_run[i], tm);
            float alpha = __expf(m_run[i] - mn);
            float p[4], psum = 0.f;
#pragma unroll
            for (int j = 0; j < 4; ++j) { p[j] = __expf(s_[i][j] - mn); psum += p[j]; }
#pragma unroll
            for (int o = 1; o < 16; o <<= 1)
                psum += __shfl_xor_sync(0xffffffffu, psum, o);
            l_run[i] = l_run[i]*alpha + psum;
            m_run[i] = mn;
#pragma unroll
            for (int j = 0; j < 4; ++j) acc_o[i][j] *= alpha;
            float4 pv = make_float4(p[0], p[1], p[2], p[3]);
            *reinterpret_cast<float4*>(Ps + (8*ty + i)*64 + 4*tx) = pv;
        }
        __syncthreads();

#pragma unroll 4
        for (int kk = 0; kk < 64; kk += 4) {
            float4 vv0 = *reinterpret_cast<const float4*>(Vs + (kk+0)*64 + 4*tx);
            float4 vv1 = *reinterpret_cast<const float4*>(Vs + (kk+1)*64 + 4*tx);
            float4 vv2 = *reinterpret_cast<const float4*>(Vs + (kk+2)*64 + 4*tx);
            float4 vv3 = *reinterpret_cast<const float4*>(Vs + (kk+3)*64 + 4*tx);
#pragma unroll
            for (int i = 0; i < 8; ++i) {
                float4 pp = *reinterpret_cast<const float4*>(Ps + (8*ty + i)*64 + kk);
                acc_o[i][0] += pp.x*vv0.x + pp.y*vv1.x + pp.z*vv2.x + pp.w*vv3.x;
                acc_o[i][1] += pp.x*vv0.y + pp.y*vv1.y + pp.z*vv2.y + pp.w*vv3.y;
                acc_o[i][2] += pp.x*vv0.z + pp.y*vv1.z + pp.z*vv2.z + pp.w*vv3.z;
                acc_o[i][3] += pp.x*vv0.w + pp.y*vv1.w + pp.z*vv2.w + pp.w*vv3.w;
            }
        }
    }

#pragma unroll
    for (int i = 0; i < 8; ++i) {
        float inv = 1.f / l_run[i];
        float4 o4 = make_float4(acc_o[i][0]*inv, acc_o[i][1]*inv,
                                acc_o[i][2]*inv, acc_o[i][3]*inv);
        *reinterpret_cast<float4*>(
            g_ctx + ((size_t)(b*SS) + q0 + 8*ty + i)*DD + (size_t)h*DHH + 4*tx) = o4;
    }
}

// ---------------- launch -----------------------------------------------------
extern "C" void kernel_launch(void* const* d_in, const int* in_sizes, int n_in,
                              void* d_out, int out_size) {
    const float* hs = (const float*)d_in[0];
    const void*  mk = d_in[1];
    const float* Wq = (const float*)d_in[2]; const float* bq = (const float*)d_in[3];
    const float* Wk = (const float*)d_in[4]; const float* bk = (const float*)d_in[5];
    const float* Wv = (const float*)d_in[6]; const float* bv = (const float*)d_in[7];
    const float* Wo = (const float*)d_in[8]; const float* bo = (const float*)d_in[9];
    float* out = (float*)d_out;

    static bool attr_set = false;
    if (!attr_set) {
        cudaFuncSetAttribute(attn_kernel,
                             cudaFuncAttributeMaxDynamicSharedMemorySize, ATTN_SMEM);
        cudaFuncSetAttribute(gemm_qkv_mma,
                             cudaFuncAttributeMaxDynamicSharedMemorySize, GT_SMEM);
        cudaFuncSetAttribute(gemm_o_mma,
                             cudaFuncAttributeMaxDynamicSharedMemorySize, GT_SMEM);
        attr_set = true;
    }

    detect_mask_kind<<<1, 32>>>((const unsigned int*)mk);
    convert_mask<<<1024, 256>>>(mk);
    transpose_w_kernel<<<dim3(32, 32, 4), dim3(32, 8)>>>(Wq, Wk, Wv, Wo);

    gemm_qkv_mma<<<dim3(8, 64, 3), 256, GT_SMEM>>>(hs, bq, bk, bv);
    transpose_k_kernel<<<dim3(SS/32, DHH/32, BB*HH), dim3(32, 8)>>>();
    attn_kernel<<<dim3(SS/128, BB*HH), 256, ATTN_SMEM>>>();
    gemm_o_mma<<<dim3(8, 64), 256, GT_SMEM>>>(bo, out);
}

// round 7
// speedup vs baseline: 1.7180x; 1.3225x over previous
#include <cuda_runtime.h>
#include <math.h>
#include <stdint.h>

#define BB   4
#define SS   2048
#define DD   1024
#define HH   16
#define DHH  64
#define MTOT (BB*SS)          // 8192
#define MASKVAL (-1e30f)

// ---------------- scratch (static device arrays; no allocation) -------------
__device__ float g_q  [(size_t)MTOT*DD];
__device__ float g_k  [(size_t)MTOT*DD];
__device__ float g_v  [(size_t)MTOT*DD];
__device__ float g_vt [(size_t)MTOT*DD];   // V transposed: [B*H][DH][S], tf32-rounded
__device__ float g_ctx[(size_t)MTOT*DD];
__device__ float g_wt [4*(size_t)DD*DD];   // W transposed to [N][K], tf32-rounded
__device__ uint32_t g_maskb[(size_t)SS*(SS/32)];   // bitmask per row
__device__ int   g_mask_kind;

__device__ __forceinline__ float to_tf32(float x) {
    float r;
    asm("cvt.rna.tf32.f32 %0, %1;" : "=f"(r) : "f"(x));
    return r;
}

// m16n8k8 tf32 warp MMA (Ampere-class; compiles at baseline sm_103 target)
__device__ __forceinline__ void mma_tf32(float4& d, const uint32_t a[4],
                                         const uint32_t b[2]) {
    asm volatile(
        "mma.sync.aligned.m16n8k8.row.col.f32.tf32.tf32.f32 "
        "{%0,%1,%2,%3}, {%4,%5,%6,%7}, {%8,%9}, {%0,%1,%2,%3};"
        : "+f"(d.x), "+f"(d.y), "+f"(d.z), "+f"(d.w)
        : "r"(a[0]), "r"(a[1]), "r"(a[2]), "r"(a[3]), "r"(b[0]), "r"(b[1]));
}

// ---------------- mask dtype detection + bitmask repack ----------------------
__global__ void detect_mask_kind(const unsigned int* __restrict__ m) {
    int lane = threadIdx.x;
    bool word_like = true;
    for (int i = lane; i < 256; i += 32) {
        unsigned int w = m[i];
        word_like = word_like && (w <= 1u || w == 0x3F800000u);
    }
    word_like = __all_sync(0xffffffffu, word_like);
    if (lane == 0) g_mask_kind = word_like ? 1 : 0;
}

__global__ void repack_mask(const void* __restrict__ mp) {
    int idx = blockIdx.x * blockDim.x + threadIdx.x;   // word index
    if (idx >= SS * (SS/32)) return;
    int row = idx >> 6, w = idx & 63;
    uint32_t bits = 0;
    if (g_mask_kind == 0) {
        const uchar4* p = (const uchar4*)mp + (size_t)row*(SS/4) + w*8;
#pragma unroll
        for (int j = 0; j < 8; ++j) {
            uchar4 c = p[j];
            bits |= (uint32_t)(c.x != 0) << (4*j + 0);
            bits |= (uint32_t)(c.y != 0) << (4*j + 1);
            bits |= (uint32_t)(c.z != 0) << (4*j + 2);
            bits |= (uint32_t)(c.w != 0) << (4*j + 3);
        }
    } else {
        const unsigned int* p = (const unsigned int*)mp + (size_t)row*SS + w*32;
#pragma unroll
        for (int j = 0; j < 32; ++j)
            bits |= (uint32_t)(p[j] != 0) << j;
    }
    g_maskb[idx] = bits;
}

// ---------------- weight transpose: W[K,N] -> WT[N,K] (tf32-rounded) ---------
__global__ void transpose_w_kernel(const float* __restrict__ W0, const float* __restrict__ W1,
                                   const float* __restrict__ W2, const float* __restrict__ W3) {
    __shared__ float tile[32][33];
    int z = blockIdx.z;
    const float* W = (z == 0) ? W0 : (z == 1) ? W1 : (z == 2) ? W2 : W3;
    float* WT = g_wt + (size_t)z*DD*DD;
    int n0 = blockIdx.x * 32, k0 = blockIdx.y * 32;
    int tx = threadIdx.x, ty = threadIdx.y;      // (32, 8)
#pragma unroll
    for (int i = ty; i < 32; i += 8)
        tile[i][tx] = to_tf32(W[(size_t)(k0 + i)*DD + n0 + tx]);
    __syncthreads();
#pragma unroll
    for (int i = ty; i < 32; i += 8)
        WT[(size_t)(n0 + i)*DD + k0 + tx] = tile[tx][i];
}

// ---------------- V transpose: [B,S,D] -> [B*H][DH][S] (tf32-rounded) --------
__global__ void transpose_v_kernel() {
    __shared__ float tile[32][33];
    int bh = blockIdx.z;
    int b  = bh >> 4, h = bh & 15;
    int s0 = blockIdx.x * 32, d0 = blockIdx.y * 32;
    int tx = threadIdx.x, ty = threadIdx.y;
#pragma unroll
    for (int i = ty; i < 32; i += 8)
        tile[i][tx] = to_tf32(g_v[(size_t)(b*SS + s0 + i)*DD + h*DHH + d0 + tx]);
    __syncthreads();
#pragma unroll
    for (int i = ty; i < 32; i += 8)
        g_vt[((size_t)bh*DHH + d0 + i)*SS + s0 + tx] = tile[tx][i];
}

// ---------------- tf32 mma.sync GEMM: C[M,1024] = A @ WT^T + bias ------------
#define GT_SMEM (2*8192*4)     // 64 KB

__device__ __forceinline__ void gemm_mma_body(const float* __restrict__ A,
                                              const float* __restrict__ Bt,
                                              const float* __restrict__ bias,
                                              float* __restrict__ C,
                                              float* sm) {
    const int t    = threadIdx.x;
    const int lane = t & 31;
    const int wid  = t >> 5;
    const int wm   = wid >> 1;
    const int wn   = wid & 1;
    const int row0 = blockIdx.y * 128;
    const int col0 = blockIdx.x * 128;

    const int srow = t >> 3;
    const int skq  = t & 7;

    float4 ra[4], rb[4];

    auto ldg_chunk = [&](int k0c) {
#pragma unroll
        for (int c = 0; c < 4; ++c) {
            int r = srow + 32*c;
            ra[c] = *reinterpret_cast<const float4*>(A  + (size_t)(row0 + r)*DD + k0c + skq*4);
            rb[c] = *reinterpret_cast<const float4*>(Bt + (size_t)(col0 + r)*DD + k0c + skq*4);
        }
    };
    auto sts_chunk = [&](float* buf) {
        float* As = buf;
        float* Bs = buf + 4096;
#pragma unroll
        for (int c = 0; c < 4; ++c) {
            int r = srow + 32*c;
            int mt = r >> 4, mr = r & 15, fr = mr & 7, half = mr >> 3;
            int nt = r >> 3, nr = r & 7;
            float va[4] = {ra[c].x, ra[c].y, ra[c].z, ra[c].w};
            float vb[4] = {rb[c].x, rb[c].y, rb[c].z, rb[c].w};
#pragma unroll
            for (int e = 0; e < 4; ++e) {
                int k  = skq*4 + e;
                int ks = k >> 3, c8 = k & 7;
                int tf = fr*4 + (c8 & 3);
                int j  = half + ((c8 >> 2) << 1);
                As[(((ks*8 + mt)*32 + tf) << 2) + j] = to_tf32(va[e]);
                int tg2 = nr*4 + (c8 & 3);
                int jb = c8 >> 2;
                Bs[(((ks*16 + nt)*32 + tg2) << 1) + jb] = vb[e];
            }
        }
    };

    float4 acc[2][8];
#pragma unroll
    for (int i = 0; i < 2; ++i)
#pragma unroll
        for (int j = 0; j < 8; ++j) acc[i][j] = make_float4(0.f, 0.f, 0.f, 0.f);

    ldg_chunk(0);
    sts_chunk(sm);
    __syncthreads();

    for (int c = 0; c < 32; ++c) {
        const float* buf = sm + (c & 1)*8192;
        const float* As = buf;
        const float* Bs = buf + 4096;
        if (c + 1 < 32) ldg_chunk((c + 1) * 32);

#pragma unroll
        for (int ks = 0; ks < 4; ++ks) {
            uint32_t af[2][4], bf[8][2];
#pragma unroll
            for (int mt2 = 0; mt2 < 2; ++mt2) {
                float4 a4 = *reinterpret_cast<const float4*>(
                    As + (((ks*8 + (wm*2 + mt2))*32 + lane) << 2));
                af[mt2][0] = __float_as_uint(a4.x);
                af[mt2][1] = __float_as_uint(a4.y);
                af[mt2][2] = __float_as_uint(a4.z);
                af[mt2][3] = __float_as_uint(a4.w);
            }
#pragma unroll
            for (int nt2 = 0; nt2 < 8; ++nt2) {
                float2 b2 = *reinterpret_cast<const float2*>(
                    Bs + (((ks*16 + (wn*8 + nt2))*32 + lane) << 1));
                bf[nt2][0] = __float_as_uint(b2.x);
                bf[nt2][1] = __float_as_uint(b2.y);
            }
#pragma unroll
            for (int mt2 = 0; mt2 < 2; ++mt2)
#pragma unroll
                for (int nt2 = 0; nt2 < 8; ++nt2)
                    mma_tf32(acc[mt2][nt2], af[mt2], bf[nt2]);
        }
        __syncthreads();
        if (c + 1 < 32) sts_chunk(sm + ((c + 1) & 1)*8192);
        __syncthreads();
    }

    const int g  = lane >> 2, tg = lane & 3;
#pragma unroll
    for (int mt2 = 0; mt2 < 2; ++mt2) {
        size_t rA = (size_t)(row0 + (wm*2 + mt2)*16 + g);
        size_t rB = rA + 8;
#pragma unroll
        for (int nt2 = 0; nt2 < 8; ++nt2) {
            int col = col0 + (wn*8 + nt2)*8 + tg*2;
            float2 b2 = *reinterpret_cast<const float2*>(bias + col);
            float2 o0 = make_float2(acc[mt2][nt2].x + b2.x, acc[mt2][nt2].y + b2.y);
            float2 o1 = make_float2(acc[mt2][nt2].z + b2.x, acc[mt2][nt2].w + b2.y);
            *reinterpret_cast<float2*>(C + rA*DD + col) = o0;
            *reinterpret_cast<float2*>(C + rB*DD + col) = o1;
        }
    }
}

__global__ __launch_bounds__(256) void gemm_qkv_mma(
    const float* __restrict__ A,
    const float* __restrict__ bq, const float* __restrict__ bk,
    const float* __restrict__ bv) {
    extern __shared__ float smf[];
    int z = blockIdx.z;
    const float* Bt   = g_wt + (size_t)z*DD*DD;
    const float* bias = (z == 0) ? bq : (z == 1) ? bk : bv;
    float* C          = (z == 0) ? g_q : (z == 1) ? g_k : g_v;
    gemm_mma_body(A, Bt, bias, C, smf);
}

__global__ __launch_bounds__(256) void gemm_o_mma(
    const float* __restrict__ bo, float* __restrict__ out) {
    extern __shared__ float smf[];
    gemm_mma_body(g_ctx, g_wt + 3*(size_t)DD*DD, bo, out, smf);
}

// ---------------- flash attention with mma.sync tf32 -------------------------
// CTA: 128 thr / 4 warps. q-tile 64 (16 rows per warp), key-tile 64.
// QK^T: 3xTF32 compensated. PV: single-pass tf32 (V pre-rounded in g_vt).
#define AT_STR 68

__global__ __launch_bounds__(128, 2) void attn_mma() {
    __shared__ float Ks [64*AT_STR];   // [key][dh]
    __shared__ float Vts[64*AT_STR];   // [dh][key] (tf32-rounded)

    const int t = threadIdx.x, lane = t & 31, w = t >> 5;
    const int g = lane >> 2, tg = lane & 3;
    const int q0 = blockIdx.x * 64;
    const int bh = blockIdx.y, b = bh >> 4, h = bh & 15;
    const int rowA = q0 + w*16 + g, rowB = rowA + 8;

    // Q fragments hi/lo (resident for whole CTA)
    uint32_t qhi[8][4], qlo[8][4];
    {
        const float* Qb = g_q + (size_t)(b*SS)*DD + h*DHH;
#pragma unroll
        for (int ks = 0; ks < 8; ++ks) {
            float v[4];
            v[0] = Qb[(size_t)rowA*DD + ks*8 + tg];
            v[1] = Qb[(size_t)rowB*DD + ks*8 + tg];
            v[2] = Qb[(size_t)rowA*DD + ks*8 + tg + 4];
            v[3] = Qb[(size_t)rowB*DD + ks*8 + tg + 4];
#pragma unroll
            for (int j = 0; j < 4; ++j) {
                float hi = to_tf32(v[j]);
                float lo = to_tf32(v[j] - hi);
                qhi[ks][j] = __float_as_uint(hi);
                qlo[ks][j] = __float_as_uint(lo);
            }
        }
    }

    float4 oacc[8];
#pragma unroll
    for (int nt = 0; nt < 8; ++nt) oacc[nt] = make_float4(0.f, 0.f, 0.f, 0.f);
    float mA = MASKVAL, mB = MASKVAL, lA = 0.f, lB = 0.f;

    for (int kt = 0; kt < 32; ++kt) {
        const int k0 = kt * 64;
        __syncthreads();
#pragma unroll
        for (int j = 0; j < 8; ++j) {
            int i = t + 128*j;
            int r = i >> 4, c4 = i & 15;
            *reinterpret_cast<float4*>(&Ks[r*AT_STR + c4*4]) =
                *reinterpret_cast<const float4*>(
                    g_k + (size_t)(b*SS + k0 + r)*DD + h*DHH + c4*4);
            *reinterpret_cast<float4*>(&Vts[r*AT_STR + c4*4]) =
                *reinterpret_cast<const float4*>(
                    g_vt + ((size_t)bh*DHH + r)*SS + k0 + c4*4);
        }
        const uint32_t mA0 = g_maskb[rowA*64 + (k0 >> 5)];
        const uint32_t mA1 = g_maskb[rowA*64 + (k0 >> 5) + 1];
        const uint32_t mB0 = g_maskb[rowB*64 + (k0 >> 5)];
        const uint32_t mB1 = g_maskb[rowB*64 + (k0 >> 5) + 1];
        __syncthreads();

        // ---- S = Q K^T (3xTF32) ----
        float4 sacc[8];
#pragma unroll
        for (int nt = 0; nt < 8; ++nt) sacc[nt] = make_float4(0.f, 0.f, 0.f, 0.f);

#pragma unroll
        for (int ks = 0; ks < 8; ++ks) {
#pragma unroll
            for (int nt = 0; nt < 8; ++nt) {
                const float* kp = &Ks[(nt*8 + g)*AT_STR + ks*8 + tg];
                float b0 = kp[0], b1 = kp[4];
                float h0 = to_tf32(b0), h1 = to_tf32(b1);
                uint32_t bhf[2] = { __float_as_uint(h0), __float_as_uint(h1) };
                uint32_t blf[2] = { __float_as_uint(to_tf32(b0 - h0)),
                                    __float_as_uint(to_tf32(b1 - h1)) };
                mma_tf32(sacc[nt], qhi[ks], bhf);
                mma_tf32(sacc[nt], qlo[ks], bhf);
                mma_tf32(sacc[nt], qhi[ks], blf);
            }
        }

        // ---- scale + mask ----
#pragma unroll
        for (int nt = 0; nt < 8; ++nt) {
            int c0 = nt*8 + 2*tg;
            uint32_t wa = (c0 & 32) ? mA1 : mA0;
            uint32_t wb = (c0 & 32) ? mB1 : mB0;
            int sh = c0 & 31;
            float sx = sacc[nt].x * 0.125f, sy = sacc[nt].y * 0.125f;
            float sz = sacc[nt].z * 0.125f, sw = sacc[nt].w * 0.125f;
            if (!((wa >> sh) & 1))       sx = MASKVAL;
            if (!((wa >> (sh + 1)) & 1)) sy = MASKVAL;
            if (!((wb >> sh) & 1))       sz = MASKVAL;
            if (!((wb >> (sh + 1)) & 1)) sw = MASKVAL;
            sacc[nt] = make_float4(sx, sy, sz, sw);
        }

        // ---- online softmax (rows rowA, rowB per lane) ----
        float tmA = MASKVAL, tmB = MASKVAL;
#pragma unroll
        for (int nt = 0; nt < 8; ++nt) {
            tmA = fmaxf(tmA, fmaxf(sacc[nt].x, sacc[nt].y));
            tmB = fmaxf(tmB, fmaxf(sacc[nt].z, sacc[nt].w));
        }
        tmA = fmaxf(tmA, __shfl_xor_sync(0xffffffffu, tmA, 1));
        tmA = fmaxf(tmA, __shfl_xor_sync(0xffffffffu, tmA, 2));
        tmB = fmaxf(tmB, __shfl_xor_sync(0xffffffffu, tmB, 1));
        tmB = fmaxf(tmB, __shfl_xor_sync(0xffffffffu, tmB, 2));

        float mnA = fmaxf(mA, tmA), mnB = fmaxf(mB, tmB);
        float aA = __expf(mA - mnA), aB = __expf(mB - mnB);
        mA = mnA; mB = mnB;

        float sumA = 0.f, sumB = 0.f;
#pragma unroll
        for (int nt = 0; nt < 8; ++nt) {
            float px = __expf(sacc[nt].x - mnA);
            float py = __expf(sacc[nt].y - mnA);
            float pz = __expf(sacc[nt].z - mnB);
            float pw = __expf(sacc[nt].w - mnB);
            sumA += px + py; sumB += pz + pw;
            sacc[nt] = make_float4(px, py, pz, pw);
        }
        sumA += __shfl_xor_sync(0xffffffffu, sumA, 1);
        sumA += __shfl_xor_sync(0xffffffffu, sumA, 2);
        sumB += __shfl_xor_sync(0xffffffffu, sumB, 1);
        sumB += __shfl_xor_sync(0xffffffffu, sumB, 2);
        lA = lA*aA + sumA;
        lB = lB*aB + sumB;
#pragma unroll
        for (int nt = 0; nt < 8; ++nt) {
            oacc[nt].x *= aA; oacc[nt].y *= aA;
            oacc[nt].z *= aB; oacc[nt].w *= aB;
        }

        // ---- O += P V : permute P (c-layout) -> a-fragment via shuffles ----
        const int srcA = g*4 + (tg >> 1), srcB = srcA + 2;
        const bool odd = tg & 1;
#pragma unroll
        for (int ks = 0; ks < 8; ++ks) {
            float xa = __shfl_sync(0xffffffffu, sacc[ks].x, srcA);
            float ya = __shfl_sync(0xffffffffu, sacc[ks].y, srcA);
            float xb = __shfl_sync(0xffffffffu, sacc[ks].x, srcB);
            float yb = __shfl_sync(0xffffffffu, sacc[ks].y, srcB);
            float za = __shfl_sync(0xffffffffu, sacc[ks].z, srcA);
            float wa = __shfl_sync(0xffffffffu, sacc[ks].w, srcA);
            float zb = __shfl_sync(0xffffffffu, sacc[ks].z, srcB);
            float wb = __shfl_sync(0xffffffffu, sacc[ks].w, srcB);
            uint32_t af[4];
            af[0] = __float_as_uint(to_tf32(odd ? ya : xa));
            af[1] = __float_as_uint(to_tf32(odd ? wa : za));
            af[2] = __float_as_uint(to_tf32(odd ? yb : xb));
            af[3] = __float_as_uint(to_tf32(odd ? wb : zb));
#pragma unroll
            for (int nt = 0; nt < 8; ++nt) {
                const float* vp = &Vts[(nt*8 + g)*AT_STR + ks*8 + tg];
                uint32_t bf[2] = { __float_as_uint(vp[0]), __float_as_uint(vp[4]) };
                mma_tf32(oacc[nt], af, bf);
            }
        }
    }

    // ---- epilogue: normalize + write ctx [B,S,H,DH] ----
    const float invA = 1.f / lA, invB = 1.f / lB;
#pragma unroll
    for (int nt = 0; nt < 8; ++nt) {
        int col = h*DHH + nt*8 + 2*tg;
        float2 oA = make_float2(oacc[nt].x * invA, oacc[nt].y * invA);
        float2 oB = make_float2(oacc[nt].z * invB, oacc[nt].w * invB);
        *reinterpret_cast<float2*>(g_ctx + (size_t)(b*SS + rowA)*DD + col) = oA;
        *reinterpret_cast<float2*>(g_ctx + (size_t)(b*SS + rowB)*DD + col) = oB;
    }
}

// ---------------- launch -----------------------------------------------------
extern "C" void kernel_launch(void* const* d_in, const int* in_sizes, int n_in,
                              void* d_out, int out_size) {
    const float* hs = (const float*)d_in[0];
    const void*  mk = d_in[1];
    const float* Wq = (const float*)d_in[2]; const float* bq = (const float*)d_in[3];
    const float* Wk = (const float*)d_in[4]; const float* bk = (const float*)d_in[5];
    const float* Wv = (const float*)d_in[6]; const float* bv = (const float*)d_in[7];
    const float* Wo = (const float*)d_in[8]; const float* bo = (const float*)d_in[9];
    float* out = (float*)d_out;

    static bool attr_set = false;
    if (!attr_set) {
        cudaFuncSetAttribute(gemm_qkv_mma,
                             cudaFuncAttributeMaxDynamicSharedMemorySize, GT_SMEM);
        cudaFuncSetAttribute(gemm_o_mma,
                             cudaFuncAttributeMaxDynamicSharedMemorySize, GT_SMEM);
        attr_set = true;
    }

    detect_mask_kind<<<1, 32>>>((const unsigned int*)mk);
    repack_mask<<<(SS*(SS/32) + 255)/256, 256>>>(mk);
    transpose_w_kernel<<<dim3(32, 32, 4), dim3(32, 8)>>>(Wq, Wk, Wv, Wo);

    gemm_qkv_mma<<<dim3(8, 64, 3), 256, GT_SMEM>>>(hs, bq, bk, bv);
    transpose_v_kernel<<<dim3(SS/32, DHH/32, BB*HH), dim3(32, 8)>>>();
    attn_mma<<<dim3(SS/64, BB*HH), 128>>>();
    gemm_o_mma<<<dim3(8, 64), 256, GT_SMEM>>>(bo, out);
}